// round 10
// baseline (speedup 1.0000x reference)
#include <cuda_runtime.h>
#include <math.h>

// ---------------------------------------------------------------------------
// Balanced Sinkhorn, persistent single-kernel, zero per-row FP64,
// 4-row ILP per warp iteration to pipeline the SHFL reduction chains.
// E' = exp((f - colmax)/eps) in [0,1] (column shift exactly invariant: the
// reference row-normalizes first) lives entirely in shared memory.
// Per-row scalars factored as r = 1/c so all products stay in fp32 range.
// ---------------------------------------------------------------------------

#define NB 16384
#define NK 256
#define GRID_P 148
#define BLOCK_P 512
#define WARPS_P 16
#define N_OUTER 10
#define INV_B 6.103515625e-05f   // 1/16384 (exact)
#define CHUNK 4
#define STRIDE (WARPS_P * CHUNK) // 64

// shared memory layout (bytes)
#define OFF_RED  0        // double[256]  2048
#define OFF_K2   2048     // double[256]  2048
#define OFF_R1   4096     // double[256]  2048
#define OFF_W    6144     // float[256]   1024
#define OFF_BUF  7168     // float[256]   1024
#define OFF_V1   8192     // float[112]    448
#define OFF_V2   8640     // float[112]    448
#define OFF_U    9088     // float[256]   1024
#define OFF_ACC  10112    // float[16*256] 16384
#define OFF_E    26496    // float[111*256] 113664
#define SMEM_TOTAL 140160

// Global state (allocation-free). tickets monotonic across graph replays;
// accumulators re-zeroed inside the kernel each launch; cmax idempotent.
static __device__ unsigned g_tickets;
static __device__ unsigned g_cmax[NK];
static __device__ double g_R1[NK];
static __device__ double g_R2[2][NK], g_R3[2][NK];
static __device__ double g_ub1[2][NK], g_ub2[2][NK], g_ub3[2][NK];

__device__ __forceinline__ float frcp(float x) {
    float r; asm("rcp.approx.f32 %0, %1;" : "=f"(r) : "f"(x)); return r;
}
// fp32-seeded double reciprocal with one DP Newton step (~2^-46)
__device__ __forceinline__ double rcpd(double x) {
    double r = (double)frcp((float)x);
    return r * (2.0 - x * r);
}
__device__ __forceinline__ unsigned encf(float x) {
    unsigned u = __float_as_uint(x);
    return (u & 0x80000000u) ? ~u : (u | 0x80000000u);
}
__device__ __forceinline__ float decf(unsigned e) {
    unsigned u = (e & 0x80000000u) ? (e & 0x7fffffffu) : ~e;
    return __uint_as_float(u);
}

// interleaved butterfly over CHUNK independent values (pipelines SHFL latency)
__device__ __forceinline__ void bfly4(float c[CHUNK]) {
#pragma unroll
    for (int m = 16; m; m >>= 1) {
#pragma unroll
        for (int i = 0; i < CHUNK; i++)
            c[i] += __shfl_xor_sync(0xffffffffu, c[i], m);
    }
}

// Grid barrier: monotonic ticket counter, all 148 blocks co-resident.
__device__ __forceinline__ void gridBar() {
    __syncthreads();
    if (threadIdx.x == 0) {
        __threadfence();
        unsigned t = atomicAdd(&g_tickets, 1u);
        unsigned target = (t / GRID_P + 1u) * GRID_P;
        for (;;) {
            unsigned v;
            asm volatile("ld.acquire.gpu.u32 %0, [%1];"
                         : "=r"(v) : "l"(&g_tickets) : "memory");
            if (v >= target) break;
            __nanosleep(32);
        }
    }
    __syncthreads();
}

// per-warp fp32 partials -> block fp32 -> global fp64 atomic
__device__ __forceinline__ void blockAcc(float* sacc, const float a[8],
                                         int lane, int warp, int tid,
                                         double* gdst) {
    float4* dst = (float4*)(sacc + warp * NK);
    dst[lane]      = make_float4(a[0], a[1], a[2], a[3]);
    dst[32 + lane] = make_float4(a[4], a[5], a[6], a[7]);
    __syncthreads();
    if (tid < NK) {
        float s = 0.f;
#pragma unroll
        for (int w = 0; w < WARPS_P; w++) s += sacc[w * NK + tid];
        atomicAdd(&gdst[tid], (double)s);
    }
}

__device__ __forceinline__ float dot8(const float* sE, int lr, int lane,
                                      float4 u0, float4 u1) {
    const float4* row = (const float4*)(sE + lr * NK);
    float4 e0 = row[lane], e1 = row[32 + lane];
    return e0.x*u0.x + e0.y*u0.y + e0.z*u0.z + e0.w*u0.w
         + e1.x*u1.x + e1.y*u1.y + e1.z*u1.z + e1.w*u1.w;
}
__device__ __forceinline__ void axpy8(const float* sE, int lr, int lane,
                                      float s, float a[8]) {
    const float4* row = (const float4*)(sE + lr * NK);
    float4 e0 = row[lane], e1 = row[32 + lane];
    a[0] += e0.x*s; a[1] += e0.y*s; a[2] += e0.z*s; a[3] += e0.w*s;
    a[4] += e1.x*s; a[5] += e1.y*s; a[6] += e1.z*s; a[7] += e1.w*s;
}

// fwd: c[b]=sum u*E; r=1/c stored; Rout[k] += E*(r/B)
__device__ __forceinline__ void fwdBody(const float* sE, const float* su,
                                        float* svf, int nrows, double* Rout,
                                        float* sacc, int lane, int warp, int tid) {
    float4 u0 = ((const float4*)su)[lane];
    float4 u1 = ((const float4*)su)[32 + lane];
    float a[8];
#pragma unroll
    for (int i = 0; i < 8; i++) a[i] = 0.f;
    for (int lr0 = warp * CHUNK; lr0 < nrows; lr0 += STRIDE) {
        float c[CHUNK];
#pragma unroll
        for (int i = 0; i < CHUNK; i++)
            c[i] = (lr0 + i < nrows) ? dot8(sE, lr0 + i, lane, u0, u1) : 1.f;
        bfly4(c);
        float vf[CHUNK];
#pragma unroll
        for (int i = 0; i < CHUNK; i++) {
            float r = frcp(fmaxf(c[i], 1e-37f));
            if (lane == 0 && lr0 + i < nrows) svf[lr0 + i] = r;
            vf[i] = r * INV_B;
        }
#pragma unroll
        for (int i = 0; i < CHUNK; i++)
            if (lr0 + i < nrows) axpy8(sE, lr0 + i, lane, vf[i], a);
    }
    blockAcc(sacc, a, lane, warp, tid, Rout);
}

// passC (3rd fwd fused with bwd layer 3):
//  c, s = sum u*E{,*P}; r=1/c; v3=r/B; cbar=(s*r)*v3; ub3 += E*(cbar - v3*P)
__device__ __forceinline__ void passCBody(const float* sE, const float* su,
                                          const float* __restrict__ fin, int rs,
                                          int nrows, double* gdst, float* sacc,
                                          int lane, int warp, int tid) {
    float4 u0 = ((const float4*)su)[lane];
    float4 u1 = ((const float4*)su)[32 + lane];
    float a[8];
#pragma unroll
    for (int i = 0; i < 8; i++) a[i] = 0.f;
    for (int lr0 = warp * CHUNK; lr0 < nrows; lr0 += STRIDE) {
        float c[CHUNK], s[CHUNK];
#pragma unroll
        for (int i = 0; i < CHUNK; i++) {
            int lr = lr0 + i;
            c[i] = 1.f; s[i] = 0.f;
            if (lr < nrows) {
                const float4* row  = (const float4*)(sE + lr * NK);
                const float4* frow = (const float4*)(fin + (size_t)(rs + lr) * NK);
                float4 e0 = row[lane], e1 = row[32 + lane];
                float4 p0 = frow[lane], p1 = frow[32 + lane];
                float t00 = e0.x*u0.x, t01 = e0.y*u0.y, t02 = e0.z*u0.z, t03 = e0.w*u0.w;
                float t10 = e1.x*u1.x, t11 = e1.y*u1.y, t12 = e1.z*u1.z, t13 = e1.w*u1.w;
                c[i] = t00+t01+t02+t03 + t10+t11+t12+t13;
                s[i] = t00*p0.x + t01*p0.y + t02*p0.z + t03*p0.w
                     + t10*p1.x + t11*p1.y + t12*p1.z + t13*p1.w;
            }
        }
        bfly4(c);
        bfly4(s);
        float cbf[CHUNK], v3f[CHUNK];
#pragma unroll
        for (int i = 0; i < CHUNK; i++) {
            float r = frcp(fmaxf(c[i], 1e-37f));
            v3f[i] = r * INV_B;
            cbf[i] = (s[i] * r) * v3f[i];     // = B*v3^2*s, overflow-safe order
        }
#pragma unroll
        for (int i = 0; i < CHUNK; i++) {
            int lr = lr0 + i;
            if (lr < nrows) {
                const float4* row  = (const float4*)(sE + lr * NK);
                const float4* frow = (const float4*)(fin + (size_t)(rs + lr) * NK);
                float4 e0 = row[lane], e1 = row[32 + lane];
                float4 p0 = frow[lane], p1 = frow[32 + lane];
                a[0] += e0.x*(cbf[i] - v3f[i]*p0.x); a[1] += e0.y*(cbf[i] - v3f[i]*p0.y);
                a[2] += e0.z*(cbf[i] - v3f[i]*p0.z); a[3] += e0.w*(cbf[i] - v3f[i]*p0.w);
                a[4] += e1.x*(cbf[i] - v3f[i]*p1.x); a[5] += e1.y*(cbf[i] - v3f[i]*p1.y);
                a[6] += e1.z*(cbf[i] - v3f[i]*p1.z); a[7] += e1.w*(cbf[i] - v3f[i]*p1.w);
            }
        }
    }
    blockAcc(sacc, a, lane, warp, tid, gdst);
}

// bwd layer: t[b]=sum rb*E; cb=-(t*r)*(r/B); ub_out += E*cb
__device__ __forceinline__ void bwdBody(const float* sE, const float* su,
                                        const float* svf, int nrows, double* gdst,
                                        float* sacc, int lane, int warp, int tid) {
    float4 b0 = ((const float4*)su)[lane];
    float4 b1 = ((const float4*)su)[32 + lane];
    float a[8];
#pragma unroll
    for (int i = 0; i < 8; i++) a[i] = 0.f;
    for (int lr0 = warp * CHUNK; lr0 < nrows; lr0 += STRIDE) {
        float t[CHUNK];
#pragma unroll
        for (int i = 0; i < CHUNK; i++)
            t[i] = (lr0 + i < nrows) ? dot8(sE, lr0 + i, lane, b0, b1) : 0.f;
        bfly4(t);
        float cbf[CHUNK];
#pragma unroll
        for (int i = 0; i < CHUNK; i++) {
            float r = (lr0 + i < nrows) ? svf[lr0 + i] : 0.f;
            cbf[i] = -(t[i] * r) * (r * INV_B);   // = -B*v^2*t, safe ordering
        }
#pragma unroll
        for (int i = 0; i < CHUNK; i++)
            if (lr0 + i < nrows) axpy8(sE, lr0 + i, lane, cbf[i], a);
    }
    blockAcc(sacc, a, lane, warp, tid, gdst);
}

// output: Q = E * (B*v3) * u3, fp32; r refined with one fp32 Newton
__device__ __forceinline__ void outBody(const float* sE, const float* su,
                                        float* __restrict__ out, int rs,
                                        int nrows, int lane, int warp) {
    float4 u0 = ((const float4*)su)[lane];
    float4 u1 = ((const float4*)su)[32 + lane];
    for (int lr0 = warp * CHUNK; lr0 < nrows; lr0 += STRIDE) {
        float c[CHUNK];
#pragma unroll
        for (int i = 0; i < CHUNK; i++)
            c[i] = (lr0 + i < nrows) ? dot8(sE, lr0 + i, lane, u0, u1) : 1.f;
        bfly4(c);
        float bs[CHUNK];
#pragma unroll
        for (int i = 0; i < CHUNK; i++) {
            float cc = fmaxf(c[i], 1e-37f);
            float r0 = frcp(cc);
            bs[i] = r0 * (2.0f - cc * r0);  // refined 1/c = B*v3
        }
#pragma unroll
        for (int i = 0; i < CHUNK; i++) {
            int lr = lr0 + i;
            if (lr < nrows) {
                const float4* row = (const float4*)(sE + lr * NK);
                float4 e0 = row[lane], e1 = row[32 + lane];
                float4 o0, o1;
                o0.x = (e0.x*bs[i])*u0.x; o0.y = (e0.y*bs[i])*u0.y;
                o0.z = (e0.z*bs[i])*u0.z; o0.w = (e0.w*bs[i])*u0.w;
                o1.x = (e1.x*bs[i])*u1.x; o1.y = (e1.y*bs[i])*u1.y;
                o1.z = (e1.z*bs[i])*u1.z; o1.w = (e1.w*bs[i])*u1.w;
                float4* orow = (float4*)(out + (size_t)(rs + lr) * NK);
                orow[lane] = o0;
                orow[32 + lane] = o1;
            }
        }
    }
}

__global__ void __launch_bounds__(BLOCK_P, 1)
sinkhorn_persist(const float* __restrict__ fin, const float* __restrict__ win,
                 float* __restrict__ out) {
    extern __shared__ char smem[];
    double* sred = (double*)(smem + OFF_RED);
    double* sK2  = (double*)(smem + OFF_K2);
    double* sR1  = (double*)(smem + OFF_R1);
    float*  sw   = (float*) (smem + OFF_W);
    float*  sbuf = (float*) (smem + OFF_BUF);
    float*  sv1  = (float*) (smem + OFF_V1);
    float*  sv2  = (float*) (smem + OFF_V2);
    float*  su   = (float*) (smem + OFF_U);
    float*  sacc = (float*) (smem + OFF_ACC);
    float*  sE   = (float*) (smem + OFF_E);

    const int tid  = threadIdx.x;
    const int lane = tid & 31, warp = tid >> 5;
    const int bid  = blockIdx.x;
    const int rs = (NB * bid) / GRID_P;
    const int re = (NB * (bid + 1)) / GRID_P;
    const int nrows = re - rs;

    // ---- phase A: zero global accumulators (block 0), local w/buf/K2 (all),
    //      column-max partials (all) ----
    if (bid == 0 && tid < NK) {
        __stcg(&g_R1[tid], 0.0);
#pragma unroll
        for (int s2 = 0; s2 < 2; s2++) {
            __stcg(&g_R2[s2][tid], 0.0);  __stcg(&g_R3[s2][tid], 0.0);
            __stcg(&g_ub1[s2][tid], 0.0); __stcg(&g_ub2[s2][tid], 0.0);
            __stcg(&g_ub3[s2][tid], 0.0);
        }
    }
    if (tid < NK) { float wv = win[tid]; sw[tid] = wv; sbuf[tid] = 0.f; su[tid] = wv; }
    __syncthreads();
    for (int s = 128; s; s >>= 1) { if (tid < s) su[tid] = fmaxf(su[tid], su[tid+s]); __syncthreads(); }
    { float m = su[0]; __syncthreads();
      float ex = 0.f;
      if (tid < NK) { ex = expf(sw[tid] - m); sred[tid] = (double)ex; }
      __syncthreads();
      for (int s = 128; s; s >>= 1) { if (tid < s) sred[tid] += sred[tid+s]; __syncthreads(); }
      float ssum = (float)sred[0]; __syncthreads();
      if (tid < NK) sK2[tid] = (double)(ex / ssum);
    }
    {   // column max: 512 threads = 2 row-halves x 256 columns
        int col = tid & 255, half = tid >> 8;
        float mx = -3.4e38f;
        for (int r = rs + half; r < re; r += 2)
            mx = fmaxf(mx, fin[(size_t)r * NK + col]);
        atomicMax(&g_cmax[col], encf(mx));   // idempotent across replays
    }
    gridBar();

    // ---- phase B: build E' = exp((f-colmax)*20) into smem; R1 = colsum ----
    {
        int col = tid & 255, half = tid >> 8;
        float Mt = decf(__ldcg(&g_cmax[col]));
        float r1p = 0.f;
        for (int r = rs + half; r < re; r += 2) {
            float e = expf((fin[(size_t)r * NK + col] - Mt) * 20.0f);
            sE[(r - rs) * NK + col] = e;
            r1p += e;
        }
        atomicAdd(&g_R1[col], (double)r1p);
    }
    gridBar();
    if (tid < NK) sR1[tid] = __ldcg(&g_R1[tid]);
    __syncthreads();

    // ---- outer loop ----
    for (int it = 0; it < N_OUTER; ++it) {
        const int s = it & 1;
        const bool last = (it == N_OUTER - 1);

        // fwd1: u1 = K2/R1 -> sv1, R2[s]
        if (tid < NK) su[tid] = (float)sK2[tid] / (float)sR1[tid];
        __syncthreads();
        fwdBody(sE, su, sv1, nrows, g_R2[s], sacc, lane, warp, tid);
        gridBar();

        // zero next iteration's accumulator slot (block 0; race-free: slot s^1
        // was last read before this barrier, first written after two more)
        if (bid == 0 && !last && tid < NK) {
            int t2 = s ^ 1;
            __stcg(&g_R2[t2][tid], 0.0);  __stcg(&g_R3[t2][tid], 0.0);
            __stcg(&g_ub1[t2][tid], 0.0); __stcg(&g_ub2[t2][tid], 0.0);
            __stcg(&g_ub3[t2][tid], 0.0);
        }

        // fwd2: u2 = K2/R2 -> sv2, R3[s]
        if (tid < NK) su[tid] = (float)sK2[tid] / (float)__ldcg(&g_R2[s][tid]);
        __syncthreads();
        fwdBody(sE, su, sv2, nrows, g_R3[s], sacc, lane, warp, tid);
        gridBar();

        if (!last) {
            // passC: u3 = K2/R3 -> ub3[s]
            if (tid < NK) su[tid] = (float)sK2[tid] / (float)__ldcg(&g_R3[s][tid]);
            __syncthreads();
            passCBody(sE, su, fin, rs, nrows, g_ub3[s], sacc, lane, warp, tid);
            gridBar();

            // bwd layer 2: rb = -ub3*K2/R3^2 (K-side, cheap DP), uses sv2 -> ub2[s]
            if (tid < NK) {
                double R = __ldcg(&g_R3[s][tid]);
                double rd = (double)frcp((float)R);
                su[tid] = (float)((-__ldcg(&g_ub3[s][tid]) * sK2[tid] * rd) * rd);
            }
            __syncthreads();
            bwdBody(sE, su, sv2, nrows, g_ub2[s], sacc, lane, warp, tid);
            gridBar();

            // bwd layer 1: rb = -ub2*K2/R2^2, uses sv1 -> ub1[s]
            if (tid < NK) {
                double R = __ldcg(&g_R2[s][tid]);
                double rd = (double)frcp((float)R);
                su[tid] = (float)((-__ldcg(&g_ub2[s][tid]) * sK2[tid] * rd) * rd);
            }
            __syncthreads();
            bwdBody(sE, su, sv1, nrows, g_ub1[s], sacc, lane, warp, tid);
            gridBar();

            // SGD update: redundant per block (deterministic, no extra barrier)
            double K2j = 0.0, kb = 0.0;
            if (tid < NK) {
                K2j = sK2[tid];
                kb = __ldcg(&g_ub1[s][tid]) * rcpd(sR1[tid])
                   + __ldcg(&g_ub2[s][tid]) * rcpd(__ldcg(&g_R2[s][tid]))
                   + __ldcg(&g_ub3[s][tid]) * rcpd(__ldcg(&g_R3[s][tid]));
                sred[tid] = kb * K2j;
            }
            __syncthreads();
            for (int st = 128; st; st >>= 1) { if (tid < st) sred[tid] += sred[tid+st]; __syncthreads(); }
            double dot = sred[0]; __syncthreads();
            float gf = 0.f;
            if (tid < NK) {
                double g = K2j*(kb - dot) + 5.0*(K2j*(1.0/256.0) - (1.0/65536.0));
                gf = (float)g;
                sred[tid] = (double)gf * (double)gf;
            }
            __syncthreads();
            for (int st = 128; st; st >>= 1) { if (tid < st) sred[tid] += sred[tid+st]; __syncthreads(); }
            float norm = (float)sqrt(sred[0]); __syncthreads();
            if (tid < NK) {
                gf *= fminf(1.0f, 1.0f/(norm + 1e-6f));
                float bf = 0.99f*sbuf[tid] + gf; sbuf[tid] = bf;
                float wv = sw[tid] - 0.1f*bf;    sw[tid]   = wv;
                su[tid] = wv;
            }
            __syncthreads();
            for (int st = 128; st; st >>= 1) { if (tid < st) su[tid] = fmaxf(su[tid], su[tid+st]); __syncthreads(); }
            float m = su[0]; __syncthreads();
            float ex = 0.f;
            if (tid < NK) { ex = expf(sw[tid] - m); sred[tid] = (double)ex; }
            __syncthreads();
            for (int st = 128; st; st >>= 1) { if (tid < st) sred[tid] += sred[tid+st]; __syncthreads(); }
            float ssum = (float)sred[0]; __syncthreads();
            if (tid < NK) sK2[tid] = (double)(ex / ssum);
            __syncthreads();
        } else {
            // final: Q uses pre-update w
            if (tid < NK) su[tid] = (float)sK2[tid] / (float)__ldcg(&g_R3[s][tid]);
            __syncthreads();
            outBody(sE, su, out, rs, nrows, lane, warp);
        }
    }
}

// ---------------------------------------------------------------------------
extern "C" void kernel_launch(void* const* d_in, const int* in_sizes, int n_in,
                              void* d_out, int out_size) {
    const float* fin = nullptr;
    const float* win = nullptr;
    for (int i = 0; i < n_in; i++) {
        if (in_sizes[i] == NB*NK)   fin = (const float*)d_in[i];
        else if (in_sizes[i] == NK) win = (const float*)d_in[i];
    }
    if (!fin) fin = (const float*)d_in[0];
    if (!win) win = (const float*)d_in[1];
    float* out = (float*)d_out;

    cudaFuncSetAttribute(sinkhorn_persist,
                         cudaFuncAttributeMaxDynamicSharedMemorySize, SMEM_TOTAL);
    sinkhorn_persist<<<GRID_P, BLOCK_P, SMEM_TOTAL>>>(fin, win, out);
}

// round 11
// speedup vs baseline: 1.1336x; 1.1336x over previous
#include <cuda_runtime.h>
#include <math.h>

// ---------------------------------------------------------------------------
// Balanced Sinkhorn, persistent single-kernel, zero per-row FP64.
// E' = exp((f - colmax)/eps) in [0,1] (column shift exactly invariant: the
// reference row-normalizes first) lives entirely in shared memory.
// Per-row scalars factored as r = 1/c so all products stay in fp32 range.
// R11: warp-reduced updates (7 bars vs 38), tight-spin grid barrier,
// fused build (one DRAM sweep), register-retained E in pass bodies.
// ---------------------------------------------------------------------------

#define NB 16384
#define NK 256
#define GRID_P 148
#define BLOCK_P 512
#define WARPS_P 16
#define N_OUTER 10
#define INV_B 6.103515625e-05f   // 1/16384 (exact)
#define CHUNK 4
#define STRIDE (WARPS_P * CHUNK)   // 64
#define CHUNK2 2
#define STRIDE2 (WARPS_P * CHUNK2) // 32

// shared memory layout (bytes)
#define OFF_RED  0        // double[256]   2048
#define OFF_K2   2048     // double[256]   2048
#define OFF_R1   4096     // double[256]   2048
#define OFF_SCL  6144     // double[4]       64 (scalar broadcast)
#define OFF_W    6208     // float[256]    1024
#define OFF_BUF  7232     // float[256]    1024
#define OFF_V1   8256     // float[112]     448
#define OFF_V2   8704     // float[112]     448
#define OFF_U    9152     // float[256]    1024
#define OFF_ACC  10176    // float[16*256] 16384
#define OFF_E    26560    // float[111*256] 113664
#define SMEM_TOTAL 140224

// Global state (allocation-free). tickets monotonic across graph replays
// (every launch performs a uniform, fixed barrier count); accumulators
// re-zeroed inside the kernel each launch; cmax idempotent.
static __device__ unsigned g_tickets;
static __device__ unsigned g_cmax[NK];
static __device__ double g_R1[NK];
static __device__ double g_R2[2][NK], g_R3[2][NK];
static __device__ double g_ub1[2][NK], g_ub2[2][NK], g_ub3[2][NK];

__device__ __forceinline__ float frcp(float x) {
    float r; asm("rcp.approx.f32 %0, %1;" : "=f"(r) : "f"(x)); return r;
}
// fp32-seeded double reciprocal with one DP Newton step (~2^-46)
__device__ __forceinline__ double rcpd(double x) {
    double r = (double)frcp((float)x);
    return r * (2.0 - x * r);
}
__device__ __forceinline__ unsigned encf(float x) {
    unsigned u = __float_as_uint(x);
    return (u & 0x80000000u) ? ~u : (u | 0x80000000u);
}
__device__ __forceinline__ float decf(unsigned e) {
    unsigned u = (e & 0x80000000u) ? (e & 0x7fffffffu) : ~e;
    return __uint_as_float(u);
}

__device__ __forceinline__ double warpRedSumD(double v) {
#pragma unroll
    for (int m = 16; m; m >>= 1) v += __shfl_xor_sync(0xffffffffu, v, m);
    return v;
}
__device__ __forceinline__ float warpRedMaxF(float v) {
#pragma unroll
    for (int m = 16; m; m >>= 1) v = fmaxf(v, __shfl_xor_sync(0xffffffffu, v, m));
    return v;
}

// interleaved butterflies (pipeline SHFL latency across independent rows)
__device__ __forceinline__ void bflyN(float* c, int n) {
#pragma unroll
    for (int m = 16; m; m >>= 1)
        for (int i = 0; i < n; i++)
            c[i] += __shfl_xor_sync(0xffffffffu, c[i], m);
}

// Grid barrier: monotonic ticket counter, all 148 blocks co-resident.
__device__ __forceinline__ void gridBar() {
    __syncthreads();
    if (threadIdx.x == 0) {
        __threadfence();
        unsigned t = atomicAdd(&g_tickets, 1u);
        unsigned target = (t / GRID_P + 1u) * GRID_P;
        unsigned v;
        do {
            asm volatile("ld.acquire.gpu.u32 %0, [%1];"
                         : "=r"(v) : "l"(&g_tickets) : "memory");
        } while (v < target);
    }
    __syncthreads();
}

// per-warp fp32 partials -> block fp32 -> global fp64 atomic
__device__ __forceinline__ void blockAcc(float* sacc, const float a[8],
                                         int lane, int warp, int tid,
                                         double* gdst) {
    float4* dst = (float4*)(sacc + warp * NK);
    dst[lane]      = make_float4(a[0], a[1], a[2], a[3]);
    dst[32 + lane] = make_float4(a[4], a[5], a[6], a[7]);
    __syncthreads();
    if (tid < NK) {
        float s = 0.f;
#pragma unroll
        for (int w = 0; w < WARPS_P; w++) s += sacc[w * NK + tid];
        atomicAdd(&gdst[tid], (double)s);
    }
}

// fwd: c[b]=sum u*E; r=1/c stored; Rout[k] += E*(r/B). E retained in regs.
__device__ __forceinline__ void fwdBody(const float* sE, const float* su,
                                        float* svf, int nrows, double* Rout,
                                        float* sacc, int lane, int warp, int tid) {
    float4 u0 = ((const float4*)su)[lane];
    float4 u1 = ((const float4*)su)[32 + lane];
    float a[8];
#pragma unroll
    for (int i = 0; i < 8; i++) a[i] = 0.f;
    for (int lr0 = warp * CHUNK; lr0 < nrows; lr0 += STRIDE) {
        float4 E0[CHUNK], E1[CHUNK];
        float c[CHUNK];
#pragma unroll
        for (int i = 0; i < CHUNK; i++) {
            if (lr0 + i < nrows) {
                const float4* row = (const float4*)(sE + (lr0 + i) * NK);
                E0[i] = row[lane]; E1[i] = row[32 + lane];
                c[i] = E0[i].x*u0.x + E0[i].y*u0.y + E0[i].z*u0.z + E0[i].w*u0.w
                     + E1[i].x*u1.x + E1[i].y*u1.y + E1[i].z*u1.z + E1[i].w*u1.w;
            } else {
                E0[i] = make_float4(0,0,0,0); E1[i] = E0[i]; c[i] = 1.f;
            }
        }
        bflyN(c, CHUNK);
#pragma unroll
        for (int i = 0; i < CHUNK; i++) {
            float r = frcp(fmaxf(c[i], 1e-37f));
            if (lane == 0 && lr0 + i < nrows) svf[lr0 + i] = r;
            float vf = r * INV_B;
            a[0] += E0[i].x*vf; a[1] += E0[i].y*vf; a[2] += E0[i].z*vf; a[3] += E0[i].w*vf;
            a[4] += E1[i].x*vf; a[5] += E1[i].y*vf; a[6] += E1[i].z*vf; a[7] += E1[i].w*vf;
        }
    }
    blockAcc(sacc, a, lane, warp, tid, Rout);
}

// passC (3rd fwd fused with bwd layer 3), CHUNK2 with E,P retained:
//  c, s = sum u*E{,*P}; r=1/c; v3=r/B; cbar=(s*r)*v3; ub3 += E*(cbar - v3*P)
__device__ __forceinline__ void passCBody(const float* sE, const float* su,
                                          const float* __restrict__ fin, int rs,
                                          int nrows, double* gdst, float* sacc,
                                          int lane, int warp, int tid) {
    float4 u0 = ((const float4*)su)[lane];
    float4 u1 = ((const float4*)su)[32 + lane];
    float a[8];
#pragma unroll
    for (int i = 0; i < 8; i++) a[i] = 0.f;
    for (int lr0 = warp * CHUNK2; lr0 < nrows; lr0 += STRIDE2) {
        float4 E0[CHUNK2], E1[CHUNK2], P0[CHUNK2], P1[CHUNK2];
        float c[CHUNK2], s[CHUNK2];
#pragma unroll
        for (int i = 0; i < CHUNK2; i++) {
            if (lr0 + i < nrows) {
                const float4* row  = (const float4*)(sE + (lr0 + i) * NK);
                const float4* frow = (const float4*)(fin + (size_t)(rs + lr0 + i) * NK);
                E0[i] = row[lane]; E1[i] = row[32 + lane];
                P0[i] = frow[lane]; P1[i] = frow[32 + lane];
                float t00 = E0[i].x*u0.x, t01 = E0[i].y*u0.y,
                      t02 = E0[i].z*u0.z, t03 = E0[i].w*u0.w;
                float t10 = E1[i].x*u1.x, t11 = E1[i].y*u1.y,
                      t12 = E1[i].z*u1.z, t13 = E1[i].w*u1.w;
                c[i] = t00+t01+t02+t03 + t10+t11+t12+t13;
                s[i] = t00*P0[i].x + t01*P0[i].y + t02*P0[i].z + t03*P0[i].w
                     + t10*P1[i].x + t11*P1[i].y + t12*P1[i].z + t13*P1[i].w;
            } else {
                E0[i] = make_float4(0,0,0,0); E1[i] = E0[i];
                P0[i] = E0[i]; P1[i] = E0[i];
                c[i] = 1.f; s[i] = 0.f;
            }
        }
        bflyN(c, CHUNK2);
        bflyN(s, CHUNK2);
#pragma unroll
        for (int i = 0; i < CHUNK2; i++) {
            float r = frcp(fmaxf(c[i], 1e-37f));
            float v3f = r * INV_B;
            float cbf = (s[i] * r) * v3f;     // = B*v3^2*s, overflow-safe order
            a[0] += E0[i].x*(cbf - v3f*P0[i].x); a[1] += E0[i].y*(cbf - v3f*P0[i].y);
            a[2] += E0[i].z*(cbf - v3f*P0[i].z); a[3] += E0[i].w*(cbf - v3f*P0[i].w);
            a[4] += E1[i].x*(cbf - v3f*P1[i].x); a[5] += E1[i].y*(cbf - v3f*P1[i].y);
            a[6] += E1[i].z*(cbf - v3f*P1[i].z); a[7] += E1[i].w*(cbf - v3f*P1[i].w);
        }
    }
    blockAcc(sacc, a, lane, warp, tid, gdst);
}

// bwd layer: t[b]=sum rb*E; cb=-(t*r)*(r/B); ub_out += E*cb. E retained.
__device__ __forceinline__ void bwdBody(const float* sE, const float* su,
                                        const float* svf, int nrows, double* gdst,
                                        float* sacc, int lane, int warp, int tid) {
    float4 b0 = ((const float4*)su)[lane];
    float4 b1 = ((const float4*)su)[32 + lane];
    float a[8];
#pragma unroll
    for (int i = 0; i < 8; i++) a[i] = 0.f;
    for (int lr0 = warp * CHUNK; lr0 < nrows; lr0 += STRIDE) {
        float4 E0[CHUNK], E1[CHUNK];
        float t[CHUNK];
#pragma unroll
        for (int i = 0; i < CHUNK; i++) {
            if (lr0 + i < nrows) {
                const float4* row = (const float4*)(sE + (lr0 + i) * NK);
                E0[i] = row[lane]; E1[i] = row[32 + lane];
                t[i] = E0[i].x*b0.x + E0[i].y*b0.y + E0[i].z*b0.z + E0[i].w*b0.w
                     + E1[i].x*b1.x + E1[i].y*b1.y + E1[i].z*b1.z + E1[i].w*b1.w;
            } else {
                E0[i] = make_float4(0,0,0,0); E1[i] = E0[i]; t[i] = 0.f;
            }
        }
        bflyN(t, CHUNK);
#pragma unroll
        for (int i = 0; i < CHUNK; i++) {
            float r = (lr0 + i < nrows) ? svf[lr0 + i] : 0.f;
            float cbf = -(t[i] * r) * (r * INV_B);   // = -B*v^2*t
            a[0] += E0[i].x*cbf; a[1] += E0[i].y*cbf; a[2] += E0[i].z*cbf; a[3] += E0[i].w*cbf;
            a[4] += E1[i].x*cbf; a[5] += E1[i].y*cbf; a[6] += E1[i].z*cbf; a[7] += E1[i].w*cbf;
        }
    }
    blockAcc(sacc, a, lane, warp, tid, gdst);
}

// output: Q = E * (B*v3) * u3, fp32; r refined with one fp32 Newton. Retained E.
__device__ __forceinline__ void outBody(const float* sE, const float* su,
                                        float* __restrict__ out, int rs,
                                        int nrows, int lane, int warp) {
    float4 u0 = ((const float4*)su)[lane];
    float4 u1 = ((const float4*)su)[32 + lane];
    for (int lr0 = warp * CHUNK; lr0 < nrows; lr0 += STRIDE) {
        float4 E0[CHUNK], E1[CHUNK];
        float c[CHUNK];
#pragma unroll
        for (int i = 0; i < CHUNK; i++) {
            if (lr0 + i < nrows) {
                const float4* row = (const float4*)(sE + (lr0 + i) * NK);
                E0[i] = row[lane]; E1[i] = row[32 + lane];
                c[i] = E0[i].x*u0.x + E0[i].y*u0.y + E0[i].z*u0.z + E0[i].w*u0.w
                     + E1[i].x*u1.x + E1[i].y*u1.y + E1[i].z*u1.z + E1[i].w*u1.w;
            } else {
                E0[i] = make_float4(0,0,0,0); E1[i] = E0[i]; c[i] = 1.f;
            }
        }
        bflyN(c, CHUNK);
#pragma unroll
        for (int i = 0; i < CHUNK; i++) {
            int lr = lr0 + i;
            if (lr < nrows) {
                float cc = fmaxf(c[i], 1e-37f);
                float r0 = frcp(cc);
                float bs = r0 * (2.0f - cc * r0);  // refined 1/c = B*v3
                float4 o0, o1;
                o0.x = (E0[i].x*bs)*u0.x; o0.y = (E0[i].y*bs)*u0.y;
                o0.z = (E0[i].z*bs)*u0.z; o0.w = (E0[i].w*bs)*u0.w;
                o1.x = (E1[i].x*bs)*u1.x; o1.y = (E1[i].y*bs)*u1.y;
                o1.z = (E1[i].z*bs)*u1.z; o1.w = (E1[i].w*bs)*u1.w;
                float4* orow = (float4*)(out + (size_t)(rs + lr) * NK);
                orow[lane] = o0;
                orow[32 + lane] = o1;
            }
        }
    }
}

__global__ void __launch_bounds__(BLOCK_P, 1)
sinkhorn_persist(const float* __restrict__ fin, const float* __restrict__ win,
                 float* __restrict__ out) {
    extern __shared__ char smem[];
    double* sred = (double*)(smem + OFF_RED);
    double* sK2  = (double*)(smem + OFF_K2);
    double* sR1  = (double*)(smem + OFF_R1);
    double* sscl = (double*)(smem + OFF_SCL);
    float*  sw   = (float*) (smem + OFF_W);
    float*  sbuf = (float*) (smem + OFF_BUF);
    float*  sv1  = (float*) (smem + OFF_V1);
    float*  sv2  = (float*) (smem + OFF_V2);
    float*  su   = (float*) (smem + OFF_U);
    float*  sacc = (float*) (smem + OFF_ACC);
    float*  sE   = (float*) (smem + OFF_E);

    const int tid  = threadIdx.x;
    const int lane = tid & 31, warp = tid >> 5;
    const int bid  = blockIdx.x;
    const int rs = (NB * bid) / GRID_P;
    const int re = (NB * (bid + 1)) / GRID_P;
    const int nrows = re - rs;

    // ---- phase A: zero globals (block 0); load w; softmax(w) -> sK2 (all);
    //      stage raw f into smem E area + column-max partials ----
    if (bid == 0 && tid < NK) {
        __stcg(&g_R1[tid], 0.0);
#pragma unroll
        for (int s2 = 0; s2 < 2; s2++) {
            __stcg(&g_R2[s2][tid], 0.0);  __stcg(&g_R3[s2][tid], 0.0);
            __stcg(&g_ub1[s2][tid], 0.0); __stcg(&g_ub2[s2][tid], 0.0);
            __stcg(&g_ub3[s2][tid], 0.0);
        }
    }
    if (tid < NK) { float wv = win[tid]; sw[tid] = wv; sbuf[tid] = 0.f; su[tid] = wv; }
    __syncthreads();
    if (warp == 0) {
        float m = -3.4e38f;
#pragma unroll
        for (int i = 0; i < 8; i++) m = fmaxf(m, su[lane + 32*i]);
        m = warpRedMaxF(m);
        if (lane == 0) sscl[0] = (double)m;
    }
    __syncthreads();
    {   float m = (float)sscl[0];
        float ex = 0.f;
        if (tid < NK) { ex = expf(sw[tid] - m); sred[tid] = (double)ex; }
        __syncthreads();
        if (warp == 0) {
            double s = 0.0;
#pragma unroll
            for (int i = 0; i < 8; i++) s += sred[lane + 32*i];
            s = warpRedSumD(s);
            if (lane == 0) sscl[0] = s;
        }
        __syncthreads();
        float ssum = (float)sscl[0];
        if (tid < NK) sK2[tid] = (double)(ex / ssum);
    }
    {   // stage f into smem + column max (thread = (col, row-half))
        int col = tid & 255, half = tid >> 8;
        float mx = -3.4e38f;
        for (int r = rs + half; r < re; r += 2) {
            float f = fin[(size_t)r * NK + col];
            sE[(r - rs) * NK + col] = f;
            mx = fmaxf(mx, f);
        }
        atomicMax(&g_cmax[col], encf(mx));   // idempotent across replays
    }
    gridBar();

    // ---- phase B: E' = exp((f-colmax)*20) in place; R1 = colsum ----
    {
        int col = tid & 255, half = tid >> 8;
        float Mt = decf(__ldcg(&g_cmax[col]));
        float r1p = 0.f;
        for (int r = rs + half; r < re; r += 2) {
            float e = expf((sE[(r - rs) * NK + col] - Mt) * 20.0f);
            sE[(r - rs) * NK + col] = e;
            r1p += e;
        }
        atomicAdd(&g_R1[col], (double)r1p);
    }
    gridBar();
    if (tid < NK) sR1[tid] = __ldcg(&g_R1[tid]);
    __syncthreads();

    // ---- outer loop ----
    for (int it = 0; it < N_OUTER; ++it) {
        const int s = it & 1;
        const bool last = (it == N_OUTER - 1);

        // fwd1: u1 = K2/R1 -> sv1, R2[s]
        if (tid < NK) su[tid] = (float)sK2[tid] / (float)sR1[tid];
        __syncthreads();
        fwdBody(sE, su, sv1, nrows, g_R2[s], sacc, lane, warp, tid);
        gridBar();

        // zero next iteration's accumulator slot (block 0; double-buffered:
        // slot s^1 was last read before this barrier, next written 2 bars later)
        if (bid == 0 && !last && tid < NK) {
            int t2 = s ^ 1;
            __stcg(&g_R2[t2][tid], 0.0);  __stcg(&g_R3[t2][tid], 0.0);
            __stcg(&g_ub1[t2][tid], 0.0); __stcg(&g_ub2[t2][tid], 0.0);
            __stcg(&g_ub3[t2][tid], 0.0);
        }

        // fwd2: u2 = K2/R2 -> sv2, R3[s]
        if (tid < NK) su[tid] = (float)sK2[tid] / (float)__ldcg(&g_R2[s][tid]);
        __syncthreads();
        fwdBody(sE, su, sv2, nrows, g_R3[s], sacc, lane, warp, tid);
        gridBar();

        if (!last) {
            // passC: u3 = K2/R3 -> ub3[s]
            if (tid < NK) su[tid] = (float)sK2[tid] / (float)__ldcg(&g_R3[s][tid]);
            __syncthreads();
            passCBody(sE, su, fin, rs, nrows, g_ub3[s], sacc, lane, warp, tid);
            gridBar();

            // bwd layer 2: rb = -ub3*K2/R3^2 (K-side DP), uses sv2 -> ub2[s]
            if (tid < NK) {
                double R = __ldcg(&g_R3[s][tid]);
                double rd = (double)frcp((float)R);
                su[tid] = (float)((-__ldcg(&g_ub3[s][tid]) * sK2[tid] * rd) * rd);
            }
            __syncthreads();
            bwdBody(sE, su, sv2, nrows, g_ub2[s], sacc, lane, warp, tid);
            gridBar();

            // bwd layer 1: rb = -ub2*K2/R2^2, uses sv1 -> ub1[s]
            if (tid < NK) {
                double R = __ldcg(&g_R2[s][tid]);
                double rd = (double)frcp((float)R);
                su[tid] = (float)((-__ldcg(&g_ub2[s][tid]) * sK2[tid] * rd) * rd);
            }
            __syncthreads();
            bwdBody(sE, su, sv1, nrows, g_ub1[s], sacc, lane, warp, tid);
            gridBar();

            // ---- SGD update, redundant per block, warp-reduced (7 bars) ----
            double K2j = 0.0, kb = 0.0;
            if (tid < NK) {
                K2j = sK2[tid];
                kb = __ldcg(&g_ub1[s][tid]) * rcpd(sR1[tid])
                   + __ldcg(&g_ub2[s][tid]) * rcpd(__ldcg(&g_R2[s][tid]))
                   + __ldcg(&g_ub3[s][tid]) * rcpd(__ldcg(&g_R3[s][tid]));
                sred[tid] = kb * K2j;
            }
            __syncthreads();
            if (warp == 0) {
                double d = 0.0;
#pragma unroll
                for (int i = 0; i < 8; i++) d += sred[lane + 32*i];
                d = warpRedSumD(d);
                if (lane == 0) sscl[0] = d;
            }
            __syncthreads();
            double dot = sscl[0];
            float gf = 0.f;
            if (tid < NK) {
                double g = K2j*(kb - dot) + 5.0*(K2j*(1.0/256.0) - (1.0/65536.0));
                gf = (float)g;
                sred[tid] = (double)gf * (double)gf;
            }
            __syncthreads();
            if (warp == 0) {
                double d = 0.0;
#pragma unroll
                for (int i = 0; i < 8; i++) d += sred[lane + 32*i];
                d = warpRedSumD(d);
                if (lane == 0) sscl[0] = sqrt(d);
            }
            __syncthreads();
            float norm = (float)sscl[0];
            if (tid < NK) {
                gf *= fminf(1.0f, 1.0f/(norm + 1e-6f));
                float bf = 0.99f*sbuf[tid] + gf; sbuf[tid] = bf;
                float wv = sw[tid] - 0.1f*bf;    sw[tid]   = wv;
                su[tid] = wv;
            }
            __syncthreads();
            if (warp == 0) {
                float m = -3.4e38f;
#pragma unroll
                for (int i = 0; i < 8; i++) m = fmaxf(m, su[lane + 32*i]);
                m = warpRedMaxF(m);
                if (lane == 0) sscl[0] = (double)m;
            }
            __syncthreads();
            float m = (float)sscl[0];
            float ex = 0.f;
            if (tid < NK) { ex = expf(sw[tid] - m); sred[tid] = (double)ex; }
            __syncthreads();
            if (warp == 0) {
                double d = 0.0;
#pragma unroll
                for (int i = 0; i < 8; i++) d += sred[lane + 32*i];
                d = warpRedSumD(d);
                if (lane == 0) sscl[0] = d;
            }
            __syncthreads();
            float ssum = (float)sscl[0];
            if (tid < NK) sK2[tid] = (double)(ex / ssum);
            __syncthreads();
        } else {
            // final: Q uses pre-update w
            if (tid < NK) su[tid] = (float)sK2[tid] / (float)__ldcg(&g_R3[s][tid]);
            __syncthreads();
            outBody(sE, su, out, rs, nrows, lane, warp);
        }
    }
}

// ---------------------------------------------------------------------------
extern "C" void kernel_launch(void* const* d_in, const int* in_sizes, int n_in,
                              void* d_out, int out_size) {
    const float* fin = nullptr;
    const float* win = nullptr;
    for (int i = 0; i < n_in; i++) {
        if (in_sizes[i] == NB*NK)   fin = (const float*)d_in[i];
        else if (in_sizes[i] == NK) win = (const float*)d_in[i];
    }
    if (!fin) fin = (const float*)d_in[0];
    if (!win) win = (const float*)d_in[1];
    float* out = (float*)d_out;

    cudaFuncSetAttribute(sinkhorn_persist,
                         cudaFuncAttributeMaxDynamicSharedMemorySize, SMEM_TOTAL);
    sinkhorn_persist<<<GRID_P, BLOCK_P, SMEM_TOTAL>>>(fin, win, out);
}